// round 2
// baseline (speedup 1.0000x reference)
#include <cuda_runtime.h>
#include <cstdint>

#define TT 1024
#define HH 50
#define PP 16

// ---- packed f32x2 helpers ----
__device__ __forceinline__ uint64_t pack2(float lo, float hi) {
    uint64_t r; asm("mov.b64 %0, {%1, %2};" : "=l"(r) : "f"(lo), "f"(hi)); return r;
}
__device__ __forceinline__ void unpack2(uint64_t v, float& lo, float& hi) {
    asm("mov.b64 {%0, %1}, %2;" : "=f"(lo), "=f"(hi) : "l"(v));
}
__device__ __forceinline__ void fma2(uint64_t& a, uint64_t x, uint64_t y) {
    asm("fma.rn.f32x2 %0, %1, %2, %0;" : "+l"(a) : "l"(x), "l"(y));
}
__device__ __forceinline__ uint64_t add2(uint64_t a, uint64_t b) {
    uint64_t r; asm("add.rn.f32x2 %0, %1, %2;" : "=l"(r) : "l"(a), "l"(b)); return r;
}

// accurate fast tanh (~1e-7), safe at +-inf
__device__ __forceinline__ float tanh_fast(float v) {
    float e = __expf(2.0f * v);
    return 1.0f - __fdividef(2.0f, e + 1.0f);
}

// 50-MAC dot against one h row, 4 independent f32x2 chains
__device__ __forceinline__ float gate_dot(const float* __restrict__ hrow,
                                          const uint64_t* __restrict__ w2,
                                          float g0)
{
    const uint64_t*   hp  = reinterpret_cast<const uint64_t*>(hrow);
    const ulonglong2* hp2 = reinterpret_cast<const ulonglong2*>(hrow);
    uint64_t a0 = pack2(g0, 0.0f), a1 = 0ull, a2 = 0ull, a3 = 0ull;
    #pragma unroll
    for (int q = 0; q < 6; ++q) {                 // pairs 0..23 (floats 0..47)
        ulonglong2 hA = hp2[2 * q];               // LDS.128 (broadcast)
        ulonglong2 hB = hp2[2 * q + 1];
        fma2(a0, w2[4 * q + 0], hA.x);
        fma2(a1, w2[4 * q + 1], hA.y);
        fma2(a2, w2[4 * q + 2], hB.x);
        fma2(a3, w2[4 * q + 3], hB.y);
    }
    fma2(a0, w2[24], hp[24]);                     // floats 48,49
    uint64_t s = add2(add2(a0, a1), add2(a2, a3));
    float lo, hi; unpack2(s, lo, hi);
    return lo + hi;
}

__global__ __launch_bounds__(224, 3)
void lstm_fused_kernel(const float* __restrict__ x,
                       const float* __restrict__ params,
                       const float* __restrict__ W_ih,
                       const float* __restrict__ W_hh,
                       const float* __restrict__ b_ih,
                       const float* __restrict__ b_hh,
                       const float* __restrict__ W_lin,
                       const float* __restrict__ b_lin,
                       float* __restrict__ out)
{
    __shared__ __align__(16) float xs[2][TT];       // two input rows
    __shared__ __align__(16) float hh[2][32][52];   // per-batch h ring, 16B rows
    __shared__ __align__(16) float wlin[72];        // W_lin padded

    const int tid  = threadIdx.x;
    const int lane = tid & 31;
    const int b0   = blockIdx.x * 2;

    // ---- init ----
    {
        const float4* x0 = reinterpret_cast<const float4*>(x + (size_t)b0 * TT);
        const float4* x1 = reinterpret_cast<const float4*>(x + (size_t)(b0 + 1) * TT);
        #pragma unroll
        for (int i = tid; i < 256; i += 224) {      // 256 float4 per row
            reinterpret_cast<float4*>(xs[0])[i] = x0[i];
            reinterpret_cast<float4*>(xs[1])[i] = x1[i];
        }
        if (tid < 72) wlin[tid] = (tid < HH + PP) ? W_lin[tid] : 0.0f;
        if (tid < 52) { hh[0][31][tid] = 0.0f; hh[1][31][tid] = 0.0f; }
    }
    const float blin = b_lin[0];

    // ---- gate mapping: thread 4j+k owns gate row r=k*50+j (quads; 200 real of 224) ----
    const bool real_gate = (tid < 4 * HH);
    const int  j = tid >> 2;
    const int  k = tid & 3;
    const int  r = k * HH + min(j, HH - 1);

    const float wih  = W_ih[r];
    const float bias = b_ih[r] + b_hh[r];
    uint64_t w2[25];
    {
        const float2* wr = reinterpret_cast<const float2*>(W_hh + r * HH);
        #pragma unroll
        for (int q = 0; q < 25; ++q) { float2 v = wr[q]; w2[q] = pack2(v.x, v.y); }
    }
    __syncthreads();

    float c0 = 0.0f, c1 = 0.0f;   // leader (k==0) cell states for both batches
    const float argscale = (k == 2) ? 1.0f : 0.5f;   // tanh for g, sigmoid-via-tanh otherwise

    #pragma unroll 1
    for (int t = 0; t < TT; ++t) {
        const int cur  = t & 31;
        const int prev = (t + 31) & 31;

        // two independent gate dots (ILP across batches)
        const float raw0 = gate_dot(&hh[0][prev][0], w2, fmaf(xs[0][t], wih, bias));
        const float raw1 = gate_dot(&hh[1][prev][0], w2, fmaf(xs[1][t], wih, bias));

        // unified activation: one tanh path, no divergence
        const float t0 = tanh_fast(argscale * raw0);
        const float t1 = tanh_fast(argscale * raw1);
        const float v0 = (k == 2) ? t0 : fmaf(0.5f, t0, 0.5f);
        const float v1 = (k == 2) ? t1 : fmaf(0.5f, t1, 0.5f);

        // quad exchange: leader gathers f,g,o (6 independent shfls, pipelined)
        const int qb = lane & ~3;
        const float f0 = __shfl_sync(0xffffffffu, v0, qb | 1);
        const float g0 = __shfl_sync(0xffffffffu, v0, qb | 2);
        const float o0 = __shfl_sync(0xffffffffu, v0, qb | 3);
        const float f1 = __shfl_sync(0xffffffffu, v1, qb | 1);
        const float g1 = __shfl_sync(0xffffffffu, v1, qb | 2);
        const float o1 = __shfl_sync(0xffffffffu, v1, qb | 3);

        if (k == 0) {
            c0 = fmaf(f0, c0, v0 * g0);
            c1 = fmaf(f1, c1, v1 * g1);
            const float h0 = o0 * tanh_fast(c0);
            const float h1 = o1 * tanh_fast(c1);
            if (real_gate) { hh[0][cur][j] = h0; hh[1][cur][j] = h1; }
        }

        // ---- bulk output flush every 32 steps: 1 thread per (batch, timestep) ----
        if ((t & 31) == 31) {
            __syncthreads();                         // h writes -> flush reads
            if (tid < 64) {
                const int bq  = tid >> 5;
                const int ttl = tid & 31;
                const int tg  = t - 31 + ttl;
                float s = blin;
                const float4* hv = reinterpret_cast<const float4*>(&hh[bq][ttl][0]);
                const float4* wv = reinterpret_cast<const float4*>(wlin);
                #pragma unroll
                for (int q = 0; q < 12; ++q) {       // floats 0..47
                    float4 h4 = hv[q]; float4 w4 = wv[q];
                    s = fmaf(h4.x, w4.x, s); s = fmaf(h4.y, w4.y, s);
                    s = fmaf(h4.z, w4.z, s); s = fmaf(h4.w, w4.w, s);
                }
                s = fmaf(hh[bq][ttl][48], wlin[48], s);
                s = fmaf(hh[bq][ttl][49], wlin[49], s);
                const float* prow = params + ((size_t)(b0 + bq) * TT + tg) * PP;
                const float4* p4 = reinterpret_cast<const float4*>(prow);
                #pragma unroll
                for (int q = 0; q < 4; ++q) {        // 16 params
                    float4 p = p4[q];
                    s = fmaf(p.x, wlin[HH + 4 * q + 0], s);
                    s = fmaf(p.y, wlin[HH + 4 * q + 1], s);
                    s = fmaf(p.z, wlin[HH + 4 * q + 2], s);
                    s = fmaf(p.w, wlin[HH + 4 * q + 3], s);
                }
                out[(size_t)(b0 + bq) * TT + tg] = s;
            }
        }

        __syncthreads();                             // step barrier (h RAW + ring reuse)
    }
}

extern "C" void kernel_launch(void* const* d_in, const int* in_sizes, int n_in,
                              void* d_out, int out_size)
{
    const float* x      = (const float*)d_in[0];
    const float* params = (const float*)d_in[1];
    const float* W_ih   = (const float*)d_in[2];
    const float* W_hh   = (const float*)d_in[3];
    const float* b_ih   = (const float*)d_in[4];
    const float* b_hh   = (const float*)d_in[5];
    const float* W_lin  = (const float*)d_in[6];
    const float* b_lin  = (const float*)d_in[7];
    float* out = (float*)d_out;

    const int B = in_sizes[0] / TT;                  // 1024
    lstm_fused_kernel<<<B / 2, 224>>>(x, params, W_ih, W_hh, b_ih, b_hh,
                                      W_lin, b_lin, out);
}

// round 3
// speedup vs baseline: 1.3121x; 1.3121x over previous
#include <cuda_runtime.h>
#include <cstdint>

#define TT 1024
#define HH 50
#define PP 16

// ---- packed f32x2 helpers ----
__device__ __forceinline__ uint64_t pack2(float lo, float hi) {
    uint64_t r; asm("mov.b64 %0, {%1, %2};" : "=l"(r) : "f"(lo), "f"(hi)); return r;
}
__device__ __forceinline__ void unpack2(uint64_t v, float& lo, float& hi) {
    asm("mov.b64 {%0, %1}, %2;" : "=f"(lo), "=f"(hi) : "l"(v));
}
__device__ __forceinline__ void fma2(uint64_t& a, uint64_t x, uint64_t y) {
    asm("fma.rn.f32x2 %0, %1, %2, %0;" : "+l"(a) : "l"(x), "l"(y));
}
__device__ __forceinline__ uint64_t add2(uint64_t a, uint64_t b) {
    uint64_t r; asm("add.rn.f32x2 %0, %1, %2;" : "=l"(r) : "l"(a), "l"(b)); return r;
}
// HW tanh (MUFU.TANH), ~2^-10 abs error
__device__ __forceinline__ float tanh_hw(float v) {
    float r; asm("tanh.approx.f32 %0, %1;" : "=f"(r) : "f"(v)); return r;
}

// dual 50-MAC dot (both batches share weights); 19 reg pairs + 6 smem-tail pairs
__device__ __forceinline__ void dual_dot(const float* __restrict__ h0,
                                         const float* __restrict__ h1,
                                         const uint64_t* __restrict__ w2,
                                         const uint64_t* __restrict__ wt,  // 6 in regs
                                         float g00, float g01,
                                         float& r0, float& r1)
{
    const ulonglong2* A2 = reinterpret_cast<const ulonglong2*>(h0);
    const ulonglong2* B2 = reinterpret_cast<const ulonglong2*>(h1);
    uint64_t a0 = pack2(g00, 0.0f), a1 = 0ull;
    uint64_t b0 = pack2(g01, 0.0f), b1 = 0ull;
    #pragma unroll
    for (int q = 0; q < 12; ++q) {                 // pairs 0..23
        ulonglong2 ha = A2[q];                     // LDS.128 broadcast
        ulonglong2 hb = B2[q];
        uint64_t wlo = (2 * q     < 19) ? w2[2 * q]     : wt[2 * q - 19];
        uint64_t whi = (2 * q + 1 < 19) ? w2[2 * q + 1] : wt[2 * q + 1 - 19];
        fma2(a0, wlo, ha.x); fma2(a1, whi, ha.y);
        fma2(b0, wlo, hb.x); fma2(b1, whi, hb.y);
    }
    const uint64_t* A1 = reinterpret_cast<const uint64_t*>(h0);
    const uint64_t* B1 = reinterpret_cast<const uint64_t*>(h1);
    fma2(a0, wt[5], A1[24]);                       // pair 24 (floats 48,49)
    fma2(b0, wt[5], B1[24]);
    float x0, x1, y0, y1;
    unpack2(add2(a0, a1), x0, x1); r0 = x0 + x1;
    unpack2(add2(b0, b1), y0, y1); r1 = y0 + y1;
}

__global__ __launch_bounds__(224, 4)
void lstm_fused_kernel(const float* __restrict__ x,
                       const float* __restrict__ params,
                       const float* __restrict__ W_ih,
                       const float* __restrict__ W_hh,
                       const float* __restrict__ b_ih,
                       const float* __restrict__ b_hh,
                       const float* __restrict__ W_lin,
                       const float* __restrict__ b_lin,
                       float* __restrict__ out)
{
    __shared__ __align__(16) float xs[2][TT];        // two input rows
    __shared__ __align__(16) float hh[2][32][52];    // per-batch h ring
    __shared__ __align__(16) float wlin[68];         // W_lin padded
    __shared__ __align__(16) uint64_t wsm[6][224];   // weight pairs 19..24, conflict-free

    const int tid  = threadIdx.x;
    const int lane = tid & 31;
    const int b0   = blockIdx.x * 2;

    // ---- init ----
    {
        const float4* x0 = reinterpret_cast<const float4*>(x + (size_t)b0 * TT);
        const float4* x1 = reinterpret_cast<const float4*>(x + (size_t)(b0 + 1) * TT);
        for (int i = tid; i < 256; i += 224) {
            reinterpret_cast<float4*>(xs[0])[i] = x0[i];
            reinterpret_cast<float4*>(xs[1])[i] = x1[i];
        }
        if (tid < 68) wlin[tid] = (tid < HH + PP) ? W_lin[tid] : 0.0f;
        if (tid < 52) { hh[0][31][tid] = 0.0f; hh[1][31][tid] = 0.0f; }
    }
    const float blin = b_lin[0];

    // ---- gate mapping: thread 4j+k owns gate row r=k*50+j ----
    const bool real_gate = (tid < 4 * HH);
    const int  j = tid >> 2;
    const int  k = tid & 3;
    const int  r = k * HH + min(j, HH - 1);

    const float wih  = W_ih[r];
    const float bias = b_ih[r] + b_hh[r];
    uint64_t w2[19];
    {
        const float2* wr = reinterpret_cast<const float2*>(W_hh + r * HH);
        #pragma unroll
        for (int q = 0; q < 19; ++q) { float2 v = wr[q]; w2[q] = pack2(v.x, v.y); }
        #pragma unroll
        for (int q = 0; q < 6; ++q) { float2 v = wr[19 + q]; wsm[q][tid] = pack2(v.x, v.y); }
    }
    __syncthreads();

    // branchless activation coefs: k==2 -> tanh(g); else sigmoid via 0.5*tanh(0.5x)+0.5
    const float ascale = (k == 2) ? 1.0f : 0.5f;
    const float cm     = (k == 2) ? 1.0f : 0.5f;
    const float ca     = (k == 2) ? 0.0f : 0.5f;

    float c0 = 0.0f, c1 = 0.0f;

    #pragma unroll 1
    for (int t = 0; t < TT; ++t) {
        const int cur  = t & 31;
        const int prev = (t + 31) & 31;

        // tail weights once per step (conflict-free LDS.64), shared across batches
        uint64_t wt[6];
        #pragma unroll
        for (int q = 0; q < 6; ++q) wt[q] = wsm[q][tid];

        float raw0, raw1;
        dual_dot(&hh[0][prev][0], &hh[1][prev][0], w2, wt,
                 fmaf(xs[0][t], wih, bias), fmaf(xs[1][t], wih, bias),
                 raw0, raw1);

        const float v0 = fmaf(cm, tanh_hw(ascale * raw0), ca);
        const float v1 = fmaf(cm, tanh_hw(ascale * raw1), ca);

        const int qb = lane & ~3;
        const float f0 = __shfl_sync(0xffffffffu, v0, qb | 1);
        const float g0 = __shfl_sync(0xffffffffu, v0, qb | 2);
        const float o0 = __shfl_sync(0xffffffffu, v0, qb | 3);
        const float f1 = __shfl_sync(0xffffffffu, v1, qb | 1);
        const float g1 = __shfl_sync(0xffffffffu, v1, qb | 2);
        const float o1 = __shfl_sync(0xffffffffu, v1, qb | 3);

        if (k == 0) {
            c0 = fmaf(f0, c0, v0 * g0);
            c1 = fmaf(f1, c1, v1 * g1);
            const float h0 = o0 * tanh_hw(c0);
            const float h1 = o1 * tanh_hw(c1);
            if (real_gate) { hh[0][cur][j] = h0; hh[1][cur][j] = h1; }
        }

        // ---- bulk output flush every 32 steps ----
        if ((t & 31) == 31) {
            __syncthreads();
            if (tid < 64) {
                const int bq  = tid >> 5;
                const int ttl = tid & 31;
                const int tg  = t - 31 + ttl;
                float s = blin;
                const float4* hv = reinterpret_cast<const float4*>(&hh[bq][ttl][0]);
                const float4* wv = reinterpret_cast<const float4*>(wlin);
                #pragma unroll
                for (int q = 0; q < 12; ++q) {
                    float4 h4 = hv[q]; float4 w4 = wv[q];
                    s = fmaf(h4.x, w4.x, s); s = fmaf(h4.y, w4.y, s);
                    s = fmaf(h4.z, w4.z, s); s = fmaf(h4.w, w4.w, s);
                }
                s = fmaf(hh[bq][ttl][48], wlin[48], s);
                s = fmaf(hh[bq][ttl][49], wlin[49], s);
                const float* prow = params + ((size_t)(b0 + bq) * TT + tg) * PP;
                const float4* p4 = reinterpret_cast<const float4*>(prow);
                #pragma unroll
                for (int q = 0; q < 4; ++q) {
                    float4 p = p4[q];
                    s = fmaf(p.x, wlin[HH + 4 * q + 0], s);
                    s = fmaf(p.y, wlin[HH + 4 * q + 1], s);
                    s = fmaf(p.z, wlin[HH + 4 * q + 2], s);
                    s = fmaf(p.w, wlin[HH + 4 * q + 3], s);
                }
                out[(size_t)(b0 + bq) * TT + tg] = s;
            }
        }

        __syncthreads();
    }
}

extern "C" void kernel_launch(void* const* d_in, const int* in_sizes, int n_in,
                              void* d_out, int out_size)
{
    const float* x      = (const float*)d_in[0];
    const float* params = (const float*)d_in[1];
    const float* W_ih   = (const float*)d_in[2];
    const float* W_hh   = (const float*)d_in[3];
    const float* b_ih   = (const float*)d_in[4];
    const float* b_hh   = (const float*)d_in[5];
    const float* W_lin  = (const float*)d_in[6];
    const float* b_lin  = (const float*)d_in[7];
    float* out = (float*)d_out;

    const int B = in_sizes[0] / TT;                  // 1024
    lstm_fused_kernel<<<B / 2, 224>>>(x, params, W_ih, W_hh, b_ih, b_hh,
                                      W_lin, b_lin, out);
}